// round 11
// baseline (speedup 1.0000x reference)
#include <cuda_runtime.h>
#include <cuda_bf16.h>
#include <cuda_fp16.h>
#include <math.h>

// Rigid-warp + trilinear resample of a 256^3 fp32 volume.
// Pass 1 (build): z-pair fp16 volume g_pairs[x][y][z] = half2(v[z], v[z+1]),
//   8 voxels/thread; block 0 thread 0 computes the voxel->voxel transform.
// Then a 48-byte D2D memcpy promotes T into __constant__ memory.
// Pass 2 (main): 2x2 outputs (i,j) per thread, specialized into a FAST
//   interior path (no clamps/selects/masks; immediate-offset loads) and a
//   general boundary path. Chained row reuse in both.
// Arithmetic fp32; tap storage fp16 (rel_err ~3e-4, threshold 1e-3).

#define DIMD 256
#define DIMH 256
#define DIMW 256
#define NVOX (DIMD * DIMH * DIMW)

__device__ float g_T[12];
__constant__ float c_T[12];
__device__ unsigned int g_pairs[NVOX];   // 64 MB static scratch (half2 per voxel)

static __device__ __forceinline__ unsigned int h2_to_u32(__half2 h) {
    return *reinterpret_cast<unsigned int*>(&h);
}
static __device__ __forceinline__ __half2 u32_to_h2(unsigned int u) {
    return *reinterpret_cast<__half2*>(&u);
}

__device__ __forceinline__ void matmul3(const float a[9], const float b[9], float c[9]) {
    #pragma unroll
    for (int i = 0; i < 3; i++)
        #pragma unroll
        for (int j = 0; j < 3; j++)
            c[i * 3 + j] = a[i * 3 + 0] * b[0 * 3 + j]
                         + a[i * 3 + 1] * b[1 * 3 + j]
                         + a[i * 3 + 2] * b[2 * 3 + j];
}

__device__ __forceinline__ void matmul4(const float a[16], const float b[16], float c[16]) {
    #pragma unroll
    for (int i = 0; i < 4; i++)
        #pragma unroll
        for (int j = 0; j < 4; j++)
            c[i * 4 + j] = a[i * 4 + 0] * b[0 * 4 + j]
                         + a[i * 4 + 1] * b[1 * 4 + j]
                         + a[i * 4 + 2] * b[2 * 4 + j]
                         + a[i * 4 + 3] * b[3 * 4 + j];
}

__device__ void inv4(const float m[16], float invOut[16]) {
    float inv[16];
    inv[0]  =  m[5]*m[10]*m[15] - m[5]*m[11]*m[14] - m[9]*m[6]*m[15] +
               m[9]*m[7]*m[14]  + m[13]*m[6]*m[11] - m[13]*m[7]*m[10];
    inv[4]  = -m[4]*m[10]*m[15] + m[4]*m[11]*m[14] + m[8]*m[6]*m[15] -
               m[8]*m[7]*m[14]  - m[12]*m[6]*m[11] + m[12]*m[7]*m[10];
    inv[8]  =  m[4]*m[9]*m[15]  - m[4]*m[11]*m[13] - m[8]*m[5]*m[15] +
               m[8]*m[7]*m[13]  + m[12]*m[5]*m[11] - m[12]*m[7]*m[9];
    inv[12] = -m[4]*m[9]*m[14]  + m[4]*m[10]*m[13] + m[8]*m[5]*m[14] -
               m[8]*m[6]*m[13]  - m[12]*m[5]*m[10] + m[12]*m[6]*m[9];
    inv[1]  = -m[1]*m[10]*m[15] + m[1]*m[11]*m[14] + m[9]*m[2]*m[15] -
               m[9]*m[3]*m[14]  - m[13]*m[2]*m[11] + m[13]*m[3]*m[10];
    inv[5]  =  m[0]*m[10]*m[15] - m[0]*m[11]*m[14] - m[8]*m[2]*m[15] +
               m[8]*m[3]*m[14]  + m[12]*m[2]*m[11] - m[12]*m[3]*m[10];
    inv[9]  = -m[0]*m[9]*m[15]  + m[0]*m[11]*m[13] + m[8]*m[1]*m[15] -
               m[8]*m[3]*m[13]  - m[12]*m[1]*m[11] + m[12]*m[3]*m[9];
    inv[13] =  m[0]*m[9]*m[14]  - m[0]*m[10]*m[13] - m[8]*m[1]*m[14] +
               m[8]*m[2]*m[13]  + m[12]*m[1]*m[10] - m[12]*m[2]*m[9];
    inv[2]  =  m[1]*m[6]*m[15]  - m[1]*m[7]*m[14]  - m[5]*m[2]*m[15] +
               m[5]*m[3]*m[14]  + m[13]*m[2]*m[7]  - m[13]*m[3]*m[6];
    inv[6]  = -m[0]*m[6]*m[15]  + m[0]*m[7]*m[14]  + m[4]*m[2]*m[15] -
               m[4]*m[3]*m[14]  - m[12]*m[2]*m[7]  + m[12]*m[3]*m[6];
    inv[10] =  m[0]*m[5]*m[15]  - m[0]*m[7]*m[13]  - m[4]*m[1]*m[15] +
               m[4]*m[3]*m[13]  + m[12]*m[1]*m[7]  - m[12]*m[3]*m[5];
    inv[14] = -m[0]*m[5]*m[14]  + m[0]*m[6]*m[13]  + m[4]*m[1]*m[14] -
               m[4]*m[2]*m[13]  - m[12]*m[1]*m[6]  + m[12]*m[2]*m[5];
    inv[3]  = -m[1]*m[6]*m[11]  + m[1]*m[7]*m[10]  + m[5]*m[2]*m[11] -
               m[5]*m[3]*m[10]  - m[9]*m[2]*m[7]   + m[9]*m[3]*m[6];
    inv[7]  =  m[0]*m[6]*m[11]  - m[0]*m[7]*m[10]  - m[4]*m[2]*m[11] +
               m[4]*m[3]*m[10]  + m[8]*m[2]*m[7]   - m[8]*m[3]*m[6];
    inv[11] = -m[0]*m[5]*m[11]  + m[0]*m[7]*m[9]   + m[4]*m[1]*m[11] -
               m[4]*m[3]*m[9]   - m[8]*m[1]*m[7]   + m[8]*m[3]*m[5];
    inv[15] =  m[0]*m[5]*m[10]  - m[0]*m[6]*m[9]   - m[4]*m[1]*m[10] +
               m[4]*m[2]*m[9]   + m[8]*m[1]*m[6]   - m[8]*m[2]*m[5];

    float det = m[0]*inv[0] + m[1]*inv[4] + m[2]*inv[8] + m[3]*inv[12];
    det = 1.0f / det;
    #pragma unroll
    for (int i = 0; i < 16; i++) invOut[i] = inv[i] * det;
}

__device__ void compute_T(const float* __restrict__ rot,
                          const float* __restrict__ tra,
                          const float* __restrict__ ref_v2r,
                          const float* __restrict__ flo_v2r) {
    float cx = cosf(rot[0]), cy = cosf(rot[1]), cz = cosf(rot[2]);
    float sx = sinf(rot[0]), sy = sinf(rot[1]), sz = sinf(rot[2]);

    float Rx[9] = {1, 0, 0,  0, cx, -sx,  0, sx, cx};
    float Ry[9] = {cy, 0, sy,  0, 1, 0,  -sy, 0, cy};
    float Rz[9] = {cz, -sz, 0,  sz, cz, 0,  0, 0, 1};
    float RxRy[9], R[9];
    matmul3(Rx, Ry, RxRy);
    matmul3(RxRy, Rz, R);

    float Trig[16] = {
        R[0], R[1], R[2], tra[0],
        R[3], R[4], R[5], tra[1],
        R[6], R[7], R[8], tra[2],
        0.f,  0.f,  0.f,  1.f
    };

    float ref[16], flo[16];
    #pragma unroll
    for (int i = 0; i < 16; i++) { ref[i] = ref_v2r[i]; flo[i] = flo_v2r[i]; }

    float flo_inv[16], A[16], T[16];
    inv4(flo, flo_inv);
    matmul4(Trig, ref, A);
    matmul4(flo_inv, A, T);

    #pragma unroll
    for (int i = 0; i < 12; i++) g_T[i] = T[i];
}

// Pass 1: build z-pair fp16 volume, 8 voxels per thread.
__global__ void __launch_bounds__(256)
build_pairs_kernel(const float* __restrict__ X,
                   const float* __restrict__ rot,
                   const float* __restrict__ tra,
                   const float* __restrict__ ref_v2r,
                   const float* __restrict__ flo_v2r) {
    if (blockIdx.x == 0 && threadIdx.x == 0)
        compute_T(rot, tra, ref_v2r, flo_v2r);

    const int t = blockIdx.x * 256 + threadIdx.x;     // 8-voxel group id
    const int base = t << 3;
    const int kb = base & 255;                        // 0..248 step 8

    const float4 v0 = __ldg((const float4*)(X + base));
    const float4 v1 = __ldg((const float4*)(X + base + 4));
    const float nxt = (kb < 248) ? __ldg(X + base + 8) : v1.w;

    uint4 o0, o1;
    o0.x = h2_to_u32(__floats2half2_rn(v0.x, v0.y));
    o0.y = h2_to_u32(__floats2half2_rn(v0.y, v0.z));
    o0.z = h2_to_u32(__floats2half2_rn(v0.z, v0.w));
    o0.w = h2_to_u32(__floats2half2_rn(v0.w, v1.x));
    o1.x = h2_to_u32(__floats2half2_rn(v1.x, v1.y));
    o1.y = h2_to_u32(__floats2half2_rn(v1.y, v1.z));
    o1.z = h2_to_u32(__floats2half2_rn(v1.z, v1.w));
    o1.w = h2_to_u32(__floats2half2_rn(v1.w, nxt));

    uint4* dst = (uint4*)(g_pairs + base);
    dst[0] = o0;
    dst[1] = o1;
}

__device__ __forceinline__ float lerpf(float a, float b, float w) {
    return fmaf(w, b - a, a);
}

__device__ __forceinline__ float interp8(float wcx, float wcy, float wcz,
                                         unsigned int u00, unsigned int u01,
                                         unsigned int u10, unsigned int u11) {
    const float2 p00 = __half22float2(u32_to_h2(u00));
    const float2 p01 = __half22float2(u32_to_h2(u01));
    const float2 p10 = __half22float2(u32_to_h2(u10));
    const float2 p11 = __half22float2(u32_to_h2(u11));
    const float c00 = lerpf(p00.x, p00.y, wcz);
    const float c01 = lerpf(p01.x, p01.y, wcz);
    const float c10 = lerpf(p10.x, p10.y, wcz);
    const float c11 = lerpf(p11.x, p11.y, wcz);
    const float c0 = lerpf(c00, c01, wcy);
    const float c1 = lerpf(c10, c11, wcy);
    return lerpf(c0, c1, wcx);
}

// General (boundary) tap: clamped indices, validity mask, variable deltas.
struct Tap {
    float wcx, wcy, wcz;
    int b00, dx, dy;
    bool ok;
};

__device__ __forceinline__ Tap make_tap(float di, float dj, float dk) {
    Tap t;
    const float MX = 255.f;
    t.ok = (di > 0.f) & (dj > 0.f) & (dk > 0.f) &
           (di <= MX) & (dj <= MX) & (dk <= MX);
    const float fx = floorf(di), fy = floorf(dj), fz = floorf(dk);
    t.wcx = di - fx; t.wcy = dj - fy; t.wcz = dk - fz;
    const int x0 = (int)fminf(fmaxf(fx, 0.f), MX);
    const int y0 = (int)fminf(fmaxf(fy, 0.f), MX);
    const int z0 = (int)fminf(fmaxf(fz, 0.f), MX);
    t.b00 = (x0 << 16) | (y0 << 8) | z0;
    t.dx = (x0 < 255) ? 65536 : 0;
    t.dy = (y0 < 255) ? 256 : 0;
    return t;
}

// Interior tap: no clamps, no mask, fixed deltas (+256 / +65536 immediates).
struct FTap { float wcx, wcy, wcz; int b00; };

__device__ __forceinline__ FTap make_ftap(float di, float dj, float dk) {
    FTap t;
    const float fx = floorf(di), fy = floorf(dj), fz = floorf(dk);
    t.wcx = di - fx; t.wcy = dj - fy; t.wcz = dk - fz;
    t.b00 = ((int)fx << 16) | ((int)fy << 8) | (int)fz;
    return t;
}

__global__ void __launch_bounds__(256)
warp_trilinear_quad4_kernel(float* __restrict__ out) {
    const int k  = threadIdx.x;              // W (stride-1)
    const int jA = (blockIdx.x & 127) << 1;  // even j
    const int iA = (blockIdx.x >> 7) << 1;   // even i

    const float T00 = c_T[0], T01 = c_T[1], T02 = c_T[2],  T03 = c_T[3];
    const float T10 = c_T[4], T11 = c_T[5], T12 = c_T[6],  T13 = c_T[7];
    const float T20 = c_T[8], T21 = c_T[9], T22 = c_T[10], T23 = c_T[11];

    const float fi = (float)iA, fj = (float)jA, fk = (float)k;
    const float diA = fmaf(T00, fi, fmaf(T01, fj, fmaf(T02, fk, T03)));
    const float djA = fmaf(T10, fi, fmaf(T11, fj, fmaf(T12, fk, T13)));
    const float dkA = fmaf(T20, fi, fmaf(T21, fj, fmaf(T22, fk, T23)));

    const float diB = diA + T01, djB = djA + T11, dkB = dkA + T21;   // (i, j+1)
    const float diC = diA + T00, djC = djA + T10, dkC = dkA + T20;   // (i+1, j)
    const float diD = diC + T01, djD = djC + T11, dkD = dkC + T21;   // (i+1, j+1)

    const int idxA = (iA << 16) | (jA << 8) | k;

    // Interior test: all 12 coords strictly inside (0, 255).
    const float mn = fminf(fminf(fminf(diA, djA), fminf(dkA, diB)),
                     fminf(fminf(fminf(djB, dkB), fminf(diC, djC)),
                           fminf(fminf(dkC, diD), fminf(djD, dkD))));
    const float mx = fmaxf(fmaxf(fmaxf(diA, djA), fmaxf(dkA, diB)),
                     fmaxf(fmaxf(fmaxf(djB, dkB), fmaxf(diC, djC)),
                           fmaxf(fmaxf(dkC, diD), fmaxf(djD, dkD))));

    if ((mn > 0.f) & (mx < 255.f)) {
        // ---------- FAST interior path ----------
        const FTap tA = make_ftap(diA, djA, dkA);
        const FTap tB = make_ftap(diB, djB, dkB);
        const FTap tC = make_ftap(diC, djC, dkC);
        const FTap tD = make_ftap(diD, djD, dkD);

        const unsigned int uA00 = __ldg(g_pairs + tA.b00);
        const unsigned int uA01 = __ldg(g_pairs + tA.b00 + 256);
        const unsigned int uA10 = __ldg(g_pairs + tA.b00 + 65536);
        const unsigned int uA11 = __ldg(g_pairs + tA.b00 + 65792);

        const bool mB = (tB.b00 == tA.b00 + 256);
        unsigned int uB00, uB10;
        if (mB) { uB00 = uA01; uB10 = uA11; }
        else    { uB00 = __ldg(g_pairs + tB.b00);
                  uB10 = __ldg(g_pairs + tB.b00 + 65536); }
        const unsigned int uB01 = __ldg(g_pairs + tB.b00 + 256);
        const unsigned int uB11 = __ldg(g_pairs + tB.b00 + 65792);

        const bool mC = (tC.b00 == tA.b00 + 65536);
        unsigned int uC00, uC01;
        if (mC) { uC00 = uA10; uC01 = uA11; }
        else    { uC00 = __ldg(g_pairs + tC.b00);
                  uC01 = __ldg(g_pairs + tC.b00 + 256); }
        const unsigned int uC10 = __ldg(g_pairs + tC.b00 + 65536);
        const unsigned int uC11 = __ldg(g_pairs + tC.b00 + 65792);

        const bool mD = (tD.b00 == tC.b00 + 256);
        unsigned int uD00, uD10;
        if (mD) { uD00 = uC01; uD10 = uC11; }
        else    { uD00 = __ldg(g_pairs + tD.b00);
                  uD10 = __ldg(g_pairs + tD.b00 + 65536); }
        const unsigned int uD01 = __ldg(g_pairs + tD.b00 + 256);
        const unsigned int uD11 = __ldg(g_pairs + tD.b00 + 65792);

        out[idxA]               = interp8(tA.wcx, tA.wcy, tA.wcz, uA00, uA01, uA10, uA11);
        out[idxA + 256]         = interp8(tB.wcx, tB.wcy, tB.wcz, uB00, uB01, uB10, uB11);
        out[idxA + 65536]       = interp8(tC.wcx, tC.wcy, tC.wcz, uC00, uC01, uC10, uC11);
        out[idxA + 65536 + 256] = interp8(tD.wcx, tD.wcy, tD.wcz, uD00, uD01, uD10, uD11);
    } else {
        // ---------- general boundary path ----------
        const Tap tA = make_tap(diA, djA, dkA);
        const Tap tB = make_tap(diB, djB, dkB);
        const Tap tC = make_tap(diC, djC, dkC);
        const Tap tD = make_tap(diD, djD, dkD);

        const unsigned int uA00 = __ldg(g_pairs + tA.b00);
        const unsigned int uA01 = __ldg(g_pairs + tA.b00 + tA.dy);
        const unsigned int uA10 = __ldg(g_pairs + tA.b00 + tA.dx);
        const unsigned int uA11 = __ldg(g_pairs + tA.b00 + tA.dx + tA.dy);

        const unsigned int uB00 = __ldg(g_pairs + tB.b00);
        const unsigned int uB01 = __ldg(g_pairs + tB.b00 + tB.dy);
        const unsigned int uB10 = __ldg(g_pairs + tB.b00 + tB.dx);
        const unsigned int uB11 = __ldg(g_pairs + tB.b00 + tB.dx + tB.dy);

        const unsigned int uC00 = __ldg(g_pairs + tC.b00);
        const unsigned int uC01 = __ldg(g_pairs + tC.b00 + tC.dy);
        const unsigned int uC10 = __ldg(g_pairs + tC.b00 + tC.dx);
        const unsigned int uC11 = __ldg(g_pairs + tC.b00 + tC.dx + tC.dy);

        const unsigned int uD00 = __ldg(g_pairs + tD.b00);
        const unsigned int uD01 = __ldg(g_pairs + tD.b00 + tD.dy);
        const unsigned int uD10 = __ldg(g_pairs + tD.b00 + tD.dx);
        const unsigned int uD11 = __ldg(g_pairs + tD.b00 + tD.dx + tD.dy);

        const float vA = interp8(tA.wcx, tA.wcy, tA.wcz, uA00, uA01, uA10, uA11);
        const float vB = interp8(tB.wcx, tB.wcy, tB.wcz, uB00, uB01, uB10, uB11);
        const float vC = interp8(tC.wcx, tC.wcy, tC.wcz, uC00, uC01, uC10, uC11);
        const float vD = interp8(tD.wcx, tD.wcy, tD.wcz, uD00, uD01, uD10, uD11);

        out[idxA]               = tA.ok ? vA : 0.f;
        out[idxA + 256]         = tB.ok ? vB : 0.f;
        out[idxA + 65536]       = tC.ok ? vC : 0.f;
        out[idxA + 65536 + 256] = tD.ok ? vD : 0.f;
    }
}

extern "C" void kernel_launch(void* const* d_in, const int* in_sizes, int n_in,
                              void* d_out, int out_size) {
    const float* image = (const float*)d_in[0];
    const float* rot   = (const float*)d_in[1];
    const float* tra   = (const float*)d_in[2];
    const float* refm  = (const float*)d_in[3];
    const float* flom  = (const float*)d_in[4];
    float* out = (float*)d_out;

    build_pairs_kernel<<<NVOX / 8 / 256, 256>>>(image, rot, tra, refm, flom);

    // Promote T from __device__ to __constant__ (48-byte D2D, capturable).
    void* src = nullptr;
    cudaGetSymbolAddress(&src, g_T);
    cudaMemcpyToSymbolAsync(c_T, src, 12 * sizeof(float), 0,
                            cudaMemcpyDeviceToDevice);

    warp_trilinear_quad4_kernel<<<(DIMD / 2) * (DIMH / 2), DIMW>>>(out);
}

// round 12
// speedup vs baseline: 1.0877x; 1.0877x over previous
#include <cuda_runtime.h>
#include <cuda_bf16.h>
#include <math.h>

// Rigid-warp + trilinear resample of a 256^3 fp32 volume — single direct pass.
// Setup kernel (1 warp) computes T = inv(flo_v2r) @ T_rig @ ref_v2r -> g_T.
// Main kernel: 2x2 (i,j) outputs per thread at fixed k, with
//   - interior fast path: no clamps/masks, immediate-offset loads
//   - chained tap reuse: B(j+1)<-A, C(i+1)<-A, D<-C via packed-base matches
//     (20 loads / 4 outputs instead of 32)
// All fp32 (rel_err ~3.6e-5).

#define DIMD 256
#define DIMH 256
#define DIMW 256

__device__ float g_T[12];

__device__ __forceinline__ void matmul3(const float a[9], const float b[9], float c[9]) {
    #pragma unroll
    for (int i = 0; i < 3; i++)
        #pragma unroll
        for (int j = 0; j < 3; j++)
            c[i * 3 + j] = a[i * 3 + 0] * b[0 * 3 + j]
                         + a[i * 3 + 1] * b[1 * 3 + j]
                         + a[i * 3 + 2] * b[2 * 3 + j];
}

__device__ __forceinline__ void matmul4(const float a[16], const float b[16], float c[16]) {
    #pragma unroll
    for (int i = 0; i < 4; i++)
        #pragma unroll
        for (int j = 0; j < 4; j++)
            c[i * 4 + j] = a[i * 4 + 0] * b[0 * 4 + j]
                         + a[i * 4 + 1] * b[1 * 4 + j]
                         + a[i * 4 + 2] * b[2 * 4 + j]
                         + a[i * 4 + 3] * b[3 * 4 + j];
}

__device__ void inv4(const float m[16], float invOut[16]) {
    float inv[16];
    inv[0]  =  m[5]*m[10]*m[15] - m[5]*m[11]*m[14] - m[9]*m[6]*m[15] +
               m[9]*m[7]*m[14]  + m[13]*m[6]*m[11] - m[13]*m[7]*m[10];
    inv[4]  = -m[4]*m[10]*m[15] + m[4]*m[11]*m[14] + m[8]*m[6]*m[15] -
               m[8]*m[7]*m[14]  - m[12]*m[6]*m[11] + m[12]*m[7]*m[10];
    inv[8]  =  m[4]*m[9]*m[15]  - m[4]*m[11]*m[13] - m[8]*m[5]*m[15] +
               m[8]*m[7]*m[13]  + m[12]*m[5]*m[11] - m[12]*m[7]*m[9];
    inv[12] = -m[4]*m[9]*m[14]  + m[4]*m[10]*m[13] + m[8]*m[5]*m[14] -
               m[8]*m[6]*m[13]  - m[12]*m[5]*m[10] + m[12]*m[6]*m[9];
    inv[1]  = -m[1]*m[10]*m[15] + m[1]*m[11]*m[14] + m[9]*m[2]*m[15] -
               m[9]*m[3]*m[14]  - m[13]*m[2]*m[11] + m[13]*m[3]*m[10];
    inv[5]  =  m[0]*m[10]*m[15] - m[0]*m[11]*m[14] - m[8]*m[2]*m[15] +
               m[8]*m[3]*m[14]  + m[12]*m[2]*m[11] - m[12]*m[3]*m[10];
    inv[9]  = -m[0]*m[9]*m[15]  + m[0]*m[11]*m[13] + m[8]*m[1]*m[15] -
               m[8]*m[3]*m[13]  - m[12]*m[1]*m[11] + m[12]*m[3]*m[9];
    inv[13] =  m[0]*m[9]*m[14]  - m[0]*m[10]*m[13] - m[8]*m[1]*m[14] +
               m[8]*m[2]*m[13]  + m[12]*m[1]*m[10] - m[12]*m[2]*m[9];
    inv[2]  =  m[1]*m[6]*m[15]  - m[1]*m[7]*m[14]  - m[5]*m[2]*m[15] +
               m[5]*m[3]*m[14]  + m[13]*m[2]*m[7]  - m[13]*m[3]*m[6];
    inv[6]  = -m[0]*m[6]*m[15]  + m[0]*m[7]*m[14]  + m[4]*m[2]*m[15] -
               m[4]*m[3]*m[14]  - m[12]*m[2]*m[7]  + m[12]*m[3]*m[6];
    inv[10] =  m[0]*m[5]*m[15]  - m[0]*m[7]*m[13]  - m[4]*m[1]*m[15] +
               m[4]*m[3]*m[13]  + m[12]*m[1]*m[7]  - m[12]*m[3]*m[5];
    inv[14] = -m[0]*m[5]*m[14]  + m[0]*m[6]*m[13]  + m[4]*m[1]*m[14] -
               m[4]*m[2]*m[13]  - m[12]*m[1]*m[6]  + m[12]*m[2]*m[5];
    inv[3]  = -m[1]*m[6]*m[11]  + m[1]*m[7]*m[10]  + m[5]*m[2]*m[11] -
               m[5]*m[3]*m[10]  - m[9]*m[2]*m[7]   + m[9]*m[3]*m[6];
    inv[7]  =  m[0]*m[6]*m[11]  - m[0]*m[7]*m[10]  - m[4]*m[2]*m[11] +
               m[4]*m[3]*m[10]  + m[8]*m[2]*m[7]   - m[8]*m[3]*m[6];
    inv[11] = -m[0]*m[5]*m[11]  + m[0]*m[7]*m[9]   + m[4]*m[1]*m[11] -
               m[4]*m[3]*m[9]   - m[8]*m[1]*m[7]   + m[8]*m[3]*m[5];
    inv[15] =  m[0]*m[5]*m[10]  - m[0]*m[6]*m[9]   - m[4]*m[1]*m[10] +
               m[4]*m[2]*m[9]   + m[8]*m[1]*m[6]   - m[8]*m[2]*m[5];

    float det = m[0]*inv[0] + m[1]*inv[4] + m[2]*inv[8] + m[3]*inv[12];
    det = 1.0f / det;
    #pragma unroll
    for (int i = 0; i < 16; i++) invOut[i] = inv[i] * det;
}

__global__ void setup_T_kernel(const float* __restrict__ rot,
                               const float* __restrict__ tra,
                               const float* __restrict__ ref_v2r,
                               const float* __restrict__ flo_v2r) {
    if (threadIdx.x != 0) return;
    float cx = cosf(rot[0]), cy = cosf(rot[1]), cz = cosf(rot[2]);
    float sx = sinf(rot[0]), sy = sinf(rot[1]), sz = sinf(rot[2]);

    float Rx[9] = {1, 0, 0,  0, cx, -sx,  0, sx, cx};
    float Ry[9] = {cy, 0, sy,  0, 1, 0,  -sy, 0, cy};
    float Rz[9] = {cz, -sz, 0,  sz, cz, 0,  0, 0, 1};
    float RxRy[9], R[9];
    matmul3(Rx, Ry, RxRy);
    matmul3(RxRy, Rz, R);

    float Trig[16] = {
        R[0], R[1], R[2], tra[0],
        R[3], R[4], R[5], tra[1],
        R[6], R[7], R[8], tra[2],
        0.f,  0.f,  0.f,  1.f
    };

    float ref[16], flo[16];
    #pragma unroll
    for (int i = 0; i < 16; i++) { ref[i] = ref_v2r[i]; flo[i] = flo_v2r[i]; }

    float flo_inv[16], A[16], T[16];
    inv4(flo, flo_inv);
    matmul4(Trig, ref, A);
    matmul4(flo_inv, A, T);

    #pragma unroll
    for (int i = 0; i < 12; i++) g_T[i] = T[i];
}

__device__ __forceinline__ float lerpf(float a, float b, float w) {
    return fmaf(w, b - a, a);
}

__device__ __forceinline__ float interp8f(float wcx, float wcy, float wcz,
                                          float v000, float v001,
                                          float v010, float v011,
                                          float v100, float v101,
                                          float v110, float v111) {
    const float c00 = lerpf(v000, v001, wcz);
    const float c01 = lerpf(v010, v011, wcz);
    const float c10 = lerpf(v100, v101, wcz);
    const float c11 = lerpf(v110, v111, wcz);
    const float c0 = lerpf(c00, c01, wcy);
    const float c1 = lerpf(c10, c11, wcy);
    return lerpf(c0, c1, wcx);
}

// General (boundary) tap.
struct Tap {
    float wcx, wcy, wcz;
    int b00, dx, dy, dz;
    bool ok;
};

__device__ __forceinline__ Tap make_tap(float di, float dj, float dk) {
    Tap t;
    const float MX = 255.f;
    t.ok = (di > 0.f) & (dj > 0.f) & (dk > 0.f) &
           (di <= MX) & (dj <= MX) & (dk <= MX);
    const float fx = floorf(di), fy = floorf(dj), fz = floorf(dk);
    t.wcx = di - fx; t.wcy = dj - fy; t.wcz = dk - fz;
    const int x0 = (int)fminf(fmaxf(fx, 0.f), MX);
    const int y0 = (int)fminf(fmaxf(fy, 0.f), MX);
    const int z0 = (int)fminf(fmaxf(fz, 0.f), MX);
    t.b00 = (x0 << 16) | (y0 << 8) | z0;
    t.dx = (x0 < 255) ? 65536 : 0;
    t.dy = (y0 < 255) ? 256 : 0;
    t.dz = (z0 < 255) ? 1 : 0;
    return t;
}

__device__ __forceinline__ float eval_tap(const float* __restrict__ X, const Tap& t) {
    const float v000 = __ldg(X + t.b00);
    const float v001 = __ldg(X + t.b00 + t.dz);
    const float v010 = __ldg(X + t.b00 + t.dy);
    const float v011 = __ldg(X + t.b00 + t.dy + t.dz);
    const float v100 = __ldg(X + t.b00 + t.dx);
    const float v101 = __ldg(X + t.b00 + t.dx + t.dz);
    const float v110 = __ldg(X + t.b00 + t.dx + t.dy);
    const float v111 = __ldg(X + t.b00 + t.dx + t.dy + t.dz);
    const float v = interp8f(t.wcx, t.wcy, t.wcz,
                             v000, v001, v010, v011, v100, v101, v110, v111);
    return t.ok ? v : 0.f;
}

// Interior tap.
struct FTap { float wcx, wcy, wcz; int b; };

__device__ __forceinline__ FTap make_ftap(float di, float dj, float dk) {
    FTap t;
    const float fx = floorf(di), fy = floorf(dj), fz = floorf(dk);
    t.wcx = di - fx; t.wcy = dj - fy; t.wcz = dk - fz;
    t.b = ((int)fx << 16) | ((int)fy << 8) | (int)fz;
    return t;
}

__global__ void __launch_bounds__(256)
warp_trilinear_direct4_kernel(const float* __restrict__ X, float* __restrict__ out) {
    const int k  = threadIdx.x;              // W (stride-1)
    const int jA = (blockIdx.x & 127) << 1;  // even j
    const int iA = (blockIdx.x >> 7) << 1;   // even i

    const float T00 = g_T[0], T01 = g_T[1], T02 = g_T[2],  T03 = g_T[3];
    const float T10 = g_T[4], T11 = g_T[5], T12 = g_T[6],  T13 = g_T[7];
    const float T20 = g_T[8], T21 = g_T[9], T22 = g_T[10], T23 = g_T[11];

    const float fi = (float)iA, fj = (float)jA, fk = (float)k;
    const float diA = fmaf(T00, fi, fmaf(T01, fj, fmaf(T02, fk, T03)));
    const float djA = fmaf(T10, fi, fmaf(T11, fj, fmaf(T12, fk, T13)));
    const float dkA = fmaf(T20, fi, fmaf(T21, fj, fmaf(T22, fk, T23)));

    const float diB = diA + T01, djB = djA + T11, dkB = dkA + T21;   // (i, j+1)
    const float diC = diA + T00, djC = djA + T10, dkC = dkA + T20;   // (i+1, j)
    const float diD = diC + T01, djD = djC + T11, dkD = dkC + T21;   // (i+1, j+1)

    const int idxA = (iA << 16) | (jA << 8) | k;

    // Interior test: all 12 coords strictly inside (0, 255).
    const float mn = fminf(fminf(fminf(diA, djA), fminf(dkA, diB)),
                     fminf(fminf(fminf(djB, dkB), fminf(diC, djC)),
                           fminf(fminf(dkC, diD), fminf(djD, dkD))));
    const float mx = fmaxf(fmaxf(fmaxf(diA, djA), fmaxf(dkA, diB)),
                     fmaxf(fmaxf(fmaxf(djB, dkB), fmaxf(diC, djC)),
                           fmaxf(fmaxf(dkC, diD), fmaxf(djD, dkD))));

    if ((mn > 0.f) & (mx < 255.f)) {
        // ---------- FAST interior path ----------
        const FTap tA = make_ftap(diA, djA, dkA);
        const FTap tB = make_ftap(diB, djB, dkB);
        const FTap tC = make_ftap(diC, djC, dkC);
        const FTap tD = make_ftap(diD, djD, dkD);

        // A: 8 primary loads
        const float a000 = __ldg(X + tA.b);
        const float a001 = __ldg(X + tA.b + 1);
        const float a010 = __ldg(X + tA.b + 256);
        const float a011 = __ldg(X + tA.b + 257);
        const float a100 = __ldg(X + tA.b + 65536);
        const float a101 = __ldg(X + tA.b + 65537);
        const float a110 = __ldg(X + tA.b + 65792);
        const float a111 = __ldg(X + tA.b + 65793);

        // B (j+1): reuse A's y1 planes when bases line up
        const bool mB = (tB.b == tA.b + 256);
        float b000, b001, b100, b101;
        if (mB) { b000 = a010; b001 = a011; b100 = a110; b101 = a111; }
        else {
            b000 = __ldg(X + tB.b);
            b001 = __ldg(X + tB.b + 1);
            b100 = __ldg(X + tB.b + 65536);
            b101 = __ldg(X + tB.b + 65537);
        }
        const float b010 = __ldg(X + tB.b + 256);
        const float b011 = __ldg(X + tB.b + 257);
        const float b110 = __ldg(X + tB.b + 65792);
        const float b111 = __ldg(X + tB.b + 65793);

        // C (i+1): reuse A's x1 planes
        const bool mC = (tC.b == tA.b + 65536);
        float c000, c001, c010, c011;
        if (mC) { c000 = a100; c001 = a101; c010 = a110; c011 = a111; }
        else {
            c000 = __ldg(X + tC.b);
            c001 = __ldg(X + tC.b + 1);
            c010 = __ldg(X + tC.b + 256);
            c011 = __ldg(X + tC.b + 257);
        }
        const float c100 = __ldg(X + tC.b + 65536);
        const float c101 = __ldg(X + tC.b + 65537);
        const float c110 = __ldg(X + tC.b + 65792);
        const float c111 = __ldg(X + tC.b + 65793);

        // D (i+1, j+1): reuse C's y1 planes
        const bool mD = (tD.b == tC.b + 256);
        float d000, d001, d100, d101;
        if (mD) { d000 = c010; d001 = c011; d100 = c110; d101 = c111; }
        else {
            d000 = __ldg(X + tD.b);
            d001 = __ldg(X + tD.b + 1);
            d100 = __ldg(X + tD.b + 65536);
            d101 = __ldg(X + tD.b + 65537);
        }
        const float d010 = __ldg(X + tD.b + 256);
        const float d011 = __ldg(X + tD.b + 257);
        const float d110 = __ldg(X + tD.b + 65792);
        const float d111 = __ldg(X + tD.b + 65793);

        out[idxA] = interp8f(tA.wcx, tA.wcy, tA.wcz,
                             a000, a001, a010, a011, a100, a101, a110, a111);
        out[idxA + 256] = interp8f(tB.wcx, tB.wcy, tB.wcz,
                             b000, b001, b010, b011, b100, b101, b110, b111);
        out[idxA + 65536] = interp8f(tC.wcx, tC.wcy, tC.wcz,
                             c000, c001, c010, c011, c100, c101, c110, c111);
        out[idxA + 65536 + 256] = interp8f(tD.wcx, tD.wcy, tD.wcz,
                             d000, d001, d010, d011, d100, d101, d110, d111);
    } else {
        // ---------- general boundary path ----------
        const Tap tA = make_tap(diA, djA, dkA);
        const Tap tB = make_tap(diB, djB, dkB);
        const Tap tC = make_tap(diC, djC, dkC);
        const Tap tD = make_tap(diD, djD, dkD);

        out[idxA]               = eval_tap(X, tA);
        out[idxA + 256]         = eval_tap(X, tB);
        out[idxA + 65536]       = eval_tap(X, tC);
        out[idxA + 65536 + 256] = eval_tap(X, tD);
    }
}

extern "C" void kernel_launch(void* const* d_in, const int* in_sizes, int n_in,
                              void* d_out, int out_size) {
    const float* image = (const float*)d_in[0];
    const float* rot   = (const float*)d_in[1];
    const float* tra   = (const float*)d_in[2];
    const float* refm  = (const float*)d_in[3];
    const float* flom  = (const float*)d_in[4];
    float* out = (float*)d_out;

    setup_T_kernel<<<1, 32>>>(rot, tra, refm, flom);
    warp_trilinear_direct4_kernel<<<(DIMD / 2) * (DIMH / 2), DIMW>>>(image, out);
}

// round 13
// speedup vs baseline: 1.1135x; 1.0237x over previous
#include <cuda_runtime.h>
#include <cuda_bf16.h>
#include <math.h>

// Rigid-warp + trilinear resample of a 256^3 fp32 volume — single direct pass.
// Setup kernel computes T = inv(flo_v2r) @ T_rig @ ref_v2r -> g_T, plus
// per-coordinate corner bounds lo/hi so the main kernel's interior test is
// 6 compares instead of a 22-op min/max tree.
// Main kernel: 2x2 (i,j) outputs per thread at fixed k, with
//   - interior fast path: no clamps/masks, immediate-offset loads
//   - chained tap reuse: B(j+1)<-A, C(i+1)<-A, D<-C (20 loads / 4 outputs)
//   - __launch_bounds__(256, 6) to hold occupancy
// All fp32.

#define DIMD 256
#define DIMH 256
#define DIMW 256

__device__ float g_T[18];   // [0..11] transform rows, [12..14] lo, [15..17] hi

__device__ __forceinline__ void matmul3(const float a[9], const float b[9], float c[9]) {
    #pragma unroll
    for (int i = 0; i < 3; i++)
        #pragma unroll
        for (int j = 0; j < 3; j++)
            c[i * 3 + j] = a[i * 3 + 0] * b[0 * 3 + j]
                         + a[i * 3 + 1] * b[1 * 3 + j]
                         + a[i * 3 + 2] * b[2 * 3 + j];
}

__device__ __forceinline__ void matmul4(const float a[16], const float b[16], float c[16]) {
    #pragma unroll
    for (int i = 0; i < 4; i++)
        #pragma unroll
        for (int j = 0; j < 4; j++)
            c[i * 4 + j] = a[i * 4 + 0] * b[0 * 4 + j]
                         + a[i * 4 + 1] * b[1 * 4 + j]
                         + a[i * 4 + 2] * b[2 * 4 + j]
                         + a[i * 4 + 3] * b[3 * 4 + j];
}

__device__ void inv4(const float m[16], float invOut[16]) {
    float inv[16];
    inv[0]  =  m[5]*m[10]*m[15] - m[5]*m[11]*m[14] - m[9]*m[6]*m[15] +
               m[9]*m[7]*m[14]  + m[13]*m[6]*m[11] - m[13]*m[7]*m[10];
    inv[4]  = -m[4]*m[10]*m[15] + m[4]*m[11]*m[14] + m[8]*m[6]*m[15] -
               m[8]*m[7]*m[14]  - m[12]*m[6]*m[11] + m[12]*m[7]*m[10];
    inv[8]  =  m[4]*m[9]*m[15]  - m[4]*m[11]*m[13] - m[8]*m[5]*m[15] +
               m[8]*m[7]*m[13]  + m[12]*m[5]*m[11] - m[12]*m[7]*m[9];
    inv[12] = -m[4]*m[9]*m[14]  + m[4]*m[10]*m[13] + m[8]*m[5]*m[14] -
               m[8]*m[6]*m[13]  - m[12]*m[5]*m[10] + m[12]*m[6]*m[9];
    inv[1]  = -m[1]*m[10]*m[15] + m[1]*m[11]*m[14] + m[9]*m[2]*m[15] -
               m[9]*m[3]*m[14]  - m[13]*m[2]*m[11] + m[13]*m[3]*m[10];
    inv[5]  =  m[0]*m[10]*m[15] - m[0]*m[11]*m[14] - m[8]*m[2]*m[15] +
               m[8]*m[3]*m[14]  + m[12]*m[2]*m[11] - m[12]*m[3]*m[10];
    inv[9]  = -m[0]*m[9]*m[15]  + m[0]*m[11]*m[13] + m[8]*m[1]*m[15] -
               m[8]*m[3]*m[13]  - m[12]*m[1]*m[11] + m[12]*m[3]*m[9];
    inv[13] =  m[0]*m[9]*m[14]  - m[0]*m[10]*m[13] - m[8]*m[1]*m[14] +
               m[8]*m[2]*m[13]  + m[12]*m[1]*m[10] - m[12]*m[2]*m[9];
    inv[2]  =  m[1]*m[6]*m[15]  - m[1]*m[7]*m[14]  - m[5]*m[2]*m[15] +
               m[5]*m[3]*m[14]  + m[13]*m[2]*m[7]  - m[13]*m[3]*m[6];
    inv[6]  = -m[0]*m[6]*m[15]  + m[0]*m[7]*m[14]  + m[4]*m[2]*m[15] -
               m[4]*m[3]*m[14]  - m[12]*m[2]*m[7]  + m[12]*m[3]*m[6];
    inv[10] =  m[0]*m[5]*m[15]  - m[0]*m[7]*m[13]  - m[4]*m[1]*m[15] +
               m[4]*m[3]*m[13]  + m[12]*m[1]*m[7]  - m[12]*m[3]*m[5];
    inv[14] = -m[0]*m[5]*m[14]  + m[0]*m[6]*m[13]  + m[4]*m[1]*m[14] -
               m[4]*m[2]*m[13]  - m[12]*m[1]*m[6]  + m[12]*m[2]*m[5];
    inv[3]  = -m[1]*m[6]*m[11]  + m[1]*m[7]*m[10]  + m[5]*m[2]*m[11] -
               m[5]*m[3]*m[10]  - m[9]*m[2]*m[7]   + m[9]*m[3]*m[6];
    inv[7]  =  m[0]*m[6]*m[11]  - m[0]*m[7]*m[10]  - m[4]*m[2]*m[11] +
               m[4]*m[3]*m[10]  + m[8]*m[2]*m[7]   - m[8]*m[3]*m[6];
    inv[11] = -m[0]*m[5]*m[11]  + m[0]*m[7]*m[9]   + m[4]*m[1]*m[11] -
               m[4]*m[3]*m[9]   - m[8]*m[1]*m[7]   + m[8]*m[3]*m[5];
    inv[15] =  m[0]*m[5]*m[10]  - m[0]*m[6]*m[9]   - m[4]*m[1]*m[10] +
               m[4]*m[2]*m[9]   + m[8]*m[1]*m[6]   - m[8]*m[2]*m[5];

    float det = m[0]*inv[0] + m[1]*inv[4] + m[2]*inv[8] + m[3]*inv[12];
    det = 1.0f / det;
    #pragma unroll
    for (int i = 0; i < 16; i++) invOut[i] = inv[i] * det;
}

__global__ void setup_T_kernel(const float* __restrict__ rot,
                               const float* __restrict__ tra,
                               const float* __restrict__ ref_v2r,
                               const float* __restrict__ flo_v2r) {
    if (threadIdx.x != 0) return;
    float cx = cosf(rot[0]), cy = cosf(rot[1]), cz = cosf(rot[2]);
    float sx = sinf(rot[0]), sy = sinf(rot[1]), sz = sinf(rot[2]);

    float Rx[9] = {1, 0, 0,  0, cx, -sx,  0, sx, cx};
    float Ry[9] = {cy, 0, sy,  0, 1, 0,  -sy, 0, cy};
    float Rz[9] = {cz, -sz, 0,  sz, cz, 0,  0, 0, 1};
    float RxRy[9], R[9];
    matmul3(Rx, Ry, RxRy);
    matmul3(RxRy, Rz, R);

    float Trig[16] = {
        R[0], R[1], R[2], tra[0],
        R[3], R[4], R[5], tra[1],
        R[6], R[7], R[8], tra[2],
        0.f,  0.f,  0.f,  1.f
    };

    float ref[16], flo[16];
    #pragma unroll
    for (int i = 0; i < 16; i++) { ref[i] = ref_v2r[i]; flo[i] = flo_v2r[i]; }

    float flo_inv[16], A[16], T[16];
    inv4(flo, flo_inv);
    matmul4(Trig, ref, A);
    matmul4(flo_inv, A, T);

    #pragma unroll
    for (int i = 0; i < 12; i++) g_T[i] = T[i];

    // Corner offset bounds for the 2x2 (i,j) output block: the 4 outputs'
    // coord c is dcA + {0, T[c][1], T[c][0], T[c][0]+T[c][1]}.
    #pragma unroll
    for (int c = 0; c < 3; c++) {
        const float t0 = T[c * 4 + 0];        // delta for i+1
        const float t1 = T[c * 4 + 1];        // delta for j+1
        const float lo = fminf(fminf(0.f, t0), fminf(t1, t0 + t1));
        const float hi = fmaxf(fmaxf(0.f, t0), fmaxf(t1, t0 + t1));
        g_T[12 + c] = lo;
        g_T[15 + c] = hi;
    }
}

__device__ __forceinline__ float lerpf(float a, float b, float w) {
    return fmaf(w, b - a, a);
}

__device__ __forceinline__ float interp8f(float wcx, float wcy, float wcz,
                                          float v000, float v001,
                                          float v010, float v011,
                                          float v100, float v101,
                                          float v110, float v111) {
    const float c00 = lerpf(v000, v001, wcz);
    const float c01 = lerpf(v010, v011, wcz);
    const float c10 = lerpf(v100, v101, wcz);
    const float c11 = lerpf(v110, v111, wcz);
    const float c0 = lerpf(c00, c01, wcy);
    const float c1 = lerpf(c10, c11, wcy);
    return lerpf(c0, c1, wcx);
}

// General (boundary) tap.
struct Tap {
    float wcx, wcy, wcz;
    int b00, dx, dy, dz;
    bool ok;
};

__device__ __forceinline__ Tap make_tap(float di, float dj, float dk) {
    Tap t;
    const float MX = 255.f;
    t.ok = (di > 0.f) & (dj > 0.f) & (dk > 0.f) &
           (di <= MX) & (dj <= MX) & (dk <= MX);
    const float fx = floorf(di), fy = floorf(dj), fz = floorf(dk);
    t.wcx = di - fx; t.wcy = dj - fy; t.wcz = dk - fz;
    const int x0 = (int)fminf(fmaxf(fx, 0.f), MX);
    const int y0 = (int)fminf(fmaxf(fy, 0.f), MX);
    const int z0 = (int)fminf(fmaxf(fz, 0.f), MX);
    t.b00 = (x0 << 16) | (y0 << 8) | z0;
    t.dx = (x0 < 255) ? 65536 : 0;
    t.dy = (y0 < 255) ? 256 : 0;
    t.dz = (z0 < 255) ? 1 : 0;
    return t;
}

__device__ __forceinline__ float eval_tap(const float* __restrict__ X, const Tap& t) {
    const float v000 = __ldg(X + t.b00);
    const float v001 = __ldg(X + t.b00 + t.dz);
    const float v010 = __ldg(X + t.b00 + t.dy);
    const float v011 = __ldg(X + t.b00 + t.dy + t.dz);
    const float v100 = __ldg(X + t.b00 + t.dx);
    const float v101 = __ldg(X + t.b00 + t.dx + t.dz);
    const float v110 = __ldg(X + t.b00 + t.dx + t.dy);
    const float v111 = __ldg(X + t.b00 + t.dx + t.dy + t.dz);
    const float v = interp8f(t.wcx, t.wcy, t.wcz,
                             v000, v001, v010, v011, v100, v101, v110, v111);
    return t.ok ? v : 0.f;
}

// Interior tap.
struct FTap { float wcx, wcy, wcz; int b; };

__device__ __forceinline__ FTap make_ftap(float di, float dj, float dk) {
    FTap t;
    const float fx = floorf(di), fy = floorf(dj), fz = floorf(dk);
    t.wcx = di - fx; t.wcy = dj - fy; t.wcz = dk - fz;
    t.b = ((int)fx << 16) | ((int)fy << 8) | (int)fz;
    return t;
}

__global__ void __launch_bounds__(256, 6)
warp_trilinear_direct4_kernel(const float* __restrict__ X, float* __restrict__ out) {
    const int k  = threadIdx.x;              // W (stride-1)
    const int jA = (blockIdx.x & 127) << 1;  // even j
    const int iA = (blockIdx.x >> 7) << 1;   // even i

    const float T00 = g_T[0], T01 = g_T[1], T02 = g_T[2],  T03 = g_T[3];
    const float T10 = g_T[4], T11 = g_T[5], T12 = g_T[6],  T13 = g_T[7];
    const float T20 = g_T[8], T21 = g_T[9], T22 = g_T[10], T23 = g_T[11];
    const float lo0 = g_T[12], lo1 = g_T[13], lo2 = g_T[14];
    const float hi0 = g_T[15], hi1 = g_T[16], hi2 = g_T[17];

    const float fi = (float)iA, fj = (float)jA, fk = (float)k;
    const float diA = fmaf(T00, fi, fmaf(T01, fj, fmaf(T02, fk, T03)));
    const float djA = fmaf(T10, fi, fmaf(T11, fj, fmaf(T12, fk, T13)));
    const float dkA = fmaf(T20, fi, fmaf(T21, fj, fmaf(T22, fk, T23)));

    const int idxA = (iA << 16) | (jA << 8) | k;

    // Interior test via precomputed corner bounds: 6 compares.
    const bool interior =
        (diA + lo0 > 0.f) & (diA + hi0 < 255.f) &
        (djA + lo1 > 0.f) & (djA + hi1 < 255.f) &
        (dkA + lo2 > 0.f) & (dkA + hi2 < 255.f);

    if (interior) {
        // ---------- FAST interior path ----------
        const FTap tA = make_ftap(diA, djA, dkA);

        // A: 8 primary loads (front-batched for MLP)
        const float a000 = __ldg(X + tA.b);
        const float a001 = __ldg(X + tA.b + 1);
        const float a010 = __ldg(X + tA.b + 256);
        const float a011 = __ldg(X + tA.b + 257);
        const float a100 = __ldg(X + tA.b + 65536);
        const float a101 = __ldg(X + tA.b + 65537);
        const float a110 = __ldg(X + tA.b + 65792);
        const float a111 = __ldg(X + tA.b + 65793);

        const FTap tB = make_ftap(diA + T01, djA + T11, dkA + T21);
        const FTap tC = make_ftap(diA + T00, djA + T10, dkA + T20);
        const FTap tD = make_ftap(diA + T00 + T01, djA + T10 + T11,
                                  dkA + T20 + T21);

        // B (j+1): reuse A's y1 planes when bases line up
        const bool mB = (tB.b == tA.b + 256);
        float b000, b001, b100, b101;
        if (mB) { b000 = a010; b001 = a011; b100 = a110; b101 = a111; }
        else {
            b000 = __ldg(X + tB.b);
            b001 = __ldg(X + tB.b + 1);
            b100 = __ldg(X + tB.b + 65536);
            b101 = __ldg(X + tB.b + 65537);
        }
        const float b010 = __ldg(X + tB.b + 256);
        const float b011 = __ldg(X + tB.b + 257);
        const float b110 = __ldg(X + tB.b + 65792);
        const float b111 = __ldg(X + tB.b + 65793);

        // C (i+1): reuse A's x1 planes
        const bool mC = (tC.b == tA.b + 65536);
        float c000, c001, c010, c011;
        if (mC) { c000 = a100; c001 = a101; c010 = a110; c011 = a111; }
        else {
            c000 = __ldg(X + tC.b);
            c001 = __ldg(X + tC.b + 1);
            c010 = __ldg(X + tC.b + 256);
            c011 = __ldg(X + tC.b + 257);
        }
        const float c100 = __ldg(X + tC.b + 65536);
        const float c101 = __ldg(X + tC.b + 65537);
        const float c110 = __ldg(X + tC.b + 65792);
        const float c111 = __ldg(X + tC.b + 65793);

        // D (i+1, j+1): reuse C's y1 planes
        const bool mD = (tD.b == tC.b + 256);
        float d000, d001, d100, d101;
        if (mD) { d000 = c010; d001 = c011; d100 = c110; d101 = c111; }
        else {
            d000 = __ldg(X + tD.b);
            d001 = __ldg(X + tD.b + 1);
            d100 = __ldg(X + tD.b + 65536);
            d101 = __ldg(X + tD.b + 65537);
        }
        const float d010 = __ldg(X + tD.b + 256);
        const float d011 = __ldg(X + tD.b + 257);
        const float d110 = __ldg(X + tD.b + 65792);
        const float d111 = __ldg(X + tD.b + 65793);

        out[idxA] = interp8f(tA.wcx, tA.wcy, tA.wcz,
                             a000, a001, a010, a011, a100, a101, a110, a111);
        out[idxA + 256] = interp8f(tB.wcx, tB.wcy, tB.wcz,
                             b000, b001, b010, b011, b100, b101, b110, b111);
        out[idxA + 65536] = interp8f(tC.wcx, tC.wcy, tC.wcz,
                             c000, c001, c010, c011, c100, c101, c110, c111);
        out[idxA + 65536 + 256] = interp8f(tD.wcx, tD.wcy, tD.wcz,
                             d000, d001, d010, d011, d100, d101, d110, d111);
    } else {
        // ---------- general boundary path ----------
        const Tap tA = make_tap(diA, djA, dkA);
        const Tap tB = make_tap(diA + T01, djA + T11, dkA + T21);
        const Tap tC = make_tap(diA + T00, djA + T10, dkA + T20);
        const Tap tD = make_tap(diA + T00 + T01, djA + T10 + T11,
                                dkA + T20 + T21);

        out[idxA]               = eval_tap(X, tA);
        out[idxA + 256]         = eval_tap(X, tB);
        out[idxA + 65536]       = eval_tap(X, tC);
        out[idxA + 65536 + 256] = eval_tap(X, tD);
    }
}

extern "C" void kernel_launch(void* const* d_in, const int* in_sizes, int n_in,
                              void* d_out, int out_size) {
    const float* image = (const float*)d_in[0];
    const float* rot   = (const float*)d_in[1];
    const float* tra   = (const float*)d_in[2];
    const float* refm  = (const float*)d_in[3];
    const float* flom  = (const float*)d_in[4];
    float* out = (float*)d_out;

    setup_T_kernel<<<1, 32>>>(rot, tra, refm, flom);
    warp_trilinear_direct4_kernel<<<(DIMD / 2) * (DIMH / 2), DIMW>>>(image, out);
}

// round 14
// speedup vs baseline: 1.1178x; 1.0039x over previous
#include <cuda_runtime.h>
#include <cuda_bf16.h>
#include <math.h>

// Rigid-warp + trilinear resample of a 256^3 fp32 volume — single direct pass.
// Setup kernel computes T = inv(flo_v2r) @ T_rig @ ref_v2r -> g_T, plus
// per-coordinate corner bounds so the interior test is 6 compares.
// Main kernel: 2x2 (i,j) outputs per thread at fixed k.
//   Interior fast path: all 4 taps computed first, then ALL 20 unconditional
//   loads issued back-to-back (MLP ~20), then BRANCHLESS predicated reuse
//   (B<-A, C<-A, D<-C), then interpolation. No clamps/masks on hot path.
// All fp32.

#define DIMD 256
#define DIMH 256
#define DIMW 256

__device__ float g_T[18];   // [0..11] transform rows, [12..14] lo, [15..17] hi

__device__ __forceinline__ void matmul3(const float a[9], const float b[9], float c[9]) {
    #pragma unroll
    for (int i = 0; i < 3; i++)
        #pragma unroll
        for (int j = 0; j < 3; j++)
            c[i * 3 + j] = a[i * 3 + 0] * b[0 * 3 + j]
                         + a[i * 3 + 1] * b[1 * 3 + j]
                         + a[i * 3 + 2] * b[2 * 3 + j];
}

__device__ __forceinline__ void matmul4(const float a[16], const float b[16], float c[16]) {
    #pragma unroll
    for (int i = 0; i < 4; i++)
        #pragma unroll
        for (int j = 0; j < 4; j++)
            c[i * 4 + j] = a[i * 4 + 0] * b[0 * 4 + j]
                         + a[i * 4 + 1] * b[1 * 4 + j]
                         + a[i * 4 + 2] * b[2 * 4 + j]
                         + a[i * 4 + 3] * b[3 * 4 + j];
}

__device__ void inv4(const float m[16], float invOut[16]) {
    float inv[16];
    inv[0]  =  m[5]*m[10]*m[15] - m[5]*m[11]*m[14] - m[9]*m[6]*m[15] +
               m[9]*m[7]*m[14]  + m[13]*m[6]*m[11] - m[13]*m[7]*m[10];
    inv[4]  = -m[4]*m[10]*m[15] + m[4]*m[11]*m[14] + m[8]*m[6]*m[15] -
               m[8]*m[7]*m[14]  - m[12]*m[6]*m[11] + m[12]*m[7]*m[10];
    inv[8]  =  m[4]*m[9]*m[15]  - m[4]*m[11]*m[13] - m[8]*m[5]*m[15] +
               m[8]*m[7]*m[13]  + m[12]*m[5]*m[11] - m[12]*m[7]*m[9];
    inv[12] = -m[4]*m[9]*m[14]  + m[4]*m[10]*m[13] + m[8]*m[5]*m[14] -
               m[8]*m[6]*m[13]  - m[12]*m[5]*m[10] + m[12]*m[6]*m[9];
    inv[1]  = -m[1]*m[10]*m[15] + m[1]*m[11]*m[14] + m[9]*m[2]*m[15] -
               m[9]*m[3]*m[14]  - m[13]*m[2]*m[11] + m[13]*m[3]*m[10];
    inv[5]  =  m[0]*m[10]*m[15] - m[0]*m[11]*m[14] - m[8]*m[2]*m[15] +
               m[8]*m[3]*m[14]  + m[12]*m[2]*m[11] - m[12]*m[3]*m[10];
    inv[9]  = -m[0]*m[9]*m[15]  + m[0]*m[11]*m[13] + m[8]*m[1]*m[15] -
               m[8]*m[3]*m[13]  - m[12]*m[1]*m[11] + m[12]*m[3]*m[9];
    inv[13] =  m[0]*m[9]*m[14]  - m[0]*m[10]*m[13] - m[8]*m[1]*m[14] +
               m[8]*m[2]*m[13]  + m[12]*m[1]*m[10] - m[12]*m[2]*m[9];
    inv[2]  =  m[1]*m[6]*m[15]  - m[1]*m[7]*m[14]  - m[5]*m[2]*m[15] +
               m[5]*m[3]*m[14]  + m[13]*m[2]*m[7]  - m[13]*m[3]*m[6];
    inv[6]  = -m[0]*m[6]*m[15]  + m[0]*m[7]*m[14]  + m[4]*m[2]*m[15] -
               m[4]*m[3]*m[14]  - m[12]*m[2]*m[7]  + m[12]*m[3]*m[6];
    inv[10] =  m[0]*m[5]*m[15]  - m[0]*m[7]*m[13]  - m[4]*m[1]*m[15] +
               m[4]*m[3]*m[13]  + m[12]*m[1]*m[7]  - m[12]*m[3]*m[5];
    inv[14] = -m[0]*m[5]*m[14]  + m[0]*m[6]*m[13]  + m[4]*m[1]*m[14] -
               m[4]*m[2]*m[13]  - m[12]*m[1]*m[6]  + m[12]*m[2]*m[5];
    inv[3]  = -m[1]*m[6]*m[11]  + m[1]*m[7]*m[10]  + m[5]*m[2]*m[11] -
               m[5]*m[3]*m[10]  - m[9]*m[2]*m[7]   + m[9]*m[3]*m[6];
    inv[7]  =  m[0]*m[6]*m[11]  - m[0]*m[7]*m[10]  - m[4]*m[2]*m[11] +
               m[4]*m[3]*m[10]  + m[8]*m[2]*m[7]   - m[8]*m[3]*m[6];
    inv[11] = -m[0]*m[5]*m[11]  + m[0]*m[7]*m[9]   + m[4]*m[1]*m[11] -
               m[4]*m[3]*m[9]   - m[8]*m[1]*m[7]   + m[8]*m[3]*m[5];
    inv[15] =  m[0]*m[5]*m[10]  - m[0]*m[6]*m[9]   - m[4]*m[1]*m[10] +
               m[4]*m[2]*m[9]   + m[8]*m[1]*m[6]   - m[8]*m[2]*m[5];

    float det = m[0]*inv[0] + m[1]*inv[4] + m[2]*inv[8] + m[3]*inv[12];
    det = 1.0f / det;
    #pragma unroll
    for (int i = 0; i < 16; i++) invOut[i] = inv[i] * det;
}

__global__ void setup_T_kernel(const float* __restrict__ rot,
                               const float* __restrict__ tra,
                               const float* __restrict__ ref_v2r,
                               const float* __restrict__ flo_v2r) {
    if (threadIdx.x != 0) return;
    float cx = cosf(rot[0]), cy = cosf(rot[1]), cz = cosf(rot[2]);
    float sx = sinf(rot[0]), sy = sinf(rot[1]), sz = sinf(rot[2]);

    float Rx[9] = {1, 0, 0,  0, cx, -sx,  0, sx, cx};
    float Ry[9] = {cy, 0, sy,  0, 1, 0,  -sy, 0, cy};
    float Rz[9] = {cz, -sz, 0,  sz, cz, 0,  0, 0, 1};
    float RxRy[9], R[9];
    matmul3(Rx, Ry, RxRy);
    matmul3(RxRy, Rz, R);

    float Trig[16] = {
        R[0], R[1], R[2], tra[0],
        R[3], R[4], R[5], tra[1],
        R[6], R[7], R[8], tra[2],
        0.f,  0.f,  0.f,  1.f
    };

    float ref[16], flo[16];
    #pragma unroll
    for (int i = 0; i < 16; i++) { ref[i] = ref_v2r[i]; flo[i] = flo_v2r[i]; }

    float flo_inv[16], A[16], T[16];
    inv4(flo, flo_inv);
    matmul4(Trig, ref, A);
    matmul4(flo_inv, A, T);

    #pragma unroll
    for (int i = 0; i < 12; i++) g_T[i] = T[i];

    #pragma unroll
    for (int c = 0; c < 3; c++) {
        const float t0 = T[c * 4 + 0];        // delta for i+1
        const float t1 = T[c * 4 + 1];        // delta for j+1
        g_T[12 + c] = fminf(fminf(0.f, t0), fminf(t1, t0 + t1));
        g_T[15 + c] = fmaxf(fmaxf(0.f, t0), fmaxf(t1, t0 + t1));
    }
}

__device__ __forceinline__ float lerpf(float a, float b, float w) {
    return fmaf(w, b - a, a);
}

__device__ __forceinline__ float interp8f(float wcx, float wcy, float wcz,
                                          float v000, float v001,
                                          float v010, float v011,
                                          float v100, float v101,
                                          float v110, float v111) {
    const float c00 = lerpf(v000, v001, wcz);
    const float c01 = lerpf(v010, v011, wcz);
    const float c10 = lerpf(v100, v101, wcz);
    const float c11 = lerpf(v110, v111, wcz);
    const float c0 = lerpf(c00, c01, wcy);
    const float c1 = lerpf(c10, c11, wcy);
    return lerpf(c0, c1, wcx);
}

// General (boundary) tap.
struct Tap {
    float wcx, wcy, wcz;
    int b00, dx, dy, dz;
    bool ok;
};

__device__ __forceinline__ Tap make_tap(float di, float dj, float dk) {
    Tap t;
    const float MX = 255.f;
    t.ok = (di > 0.f) & (dj > 0.f) & (dk > 0.f) &
           (di <= MX) & (dj <= MX) & (dk <= MX);
    const float fx = floorf(di), fy = floorf(dj), fz = floorf(dk);
    t.wcx = di - fx; t.wcy = dj - fy; t.wcz = dk - fz;
    const int x0 = (int)fminf(fmaxf(fx, 0.f), MX);
    const int y0 = (int)fminf(fmaxf(fy, 0.f), MX);
    const int z0 = (int)fminf(fmaxf(fz, 0.f), MX);
    t.b00 = (x0 << 16) | (y0 << 8) | z0;
    t.dx = (x0 < 255) ? 65536 : 0;
    t.dy = (y0 < 255) ? 256 : 0;
    t.dz = (z0 < 255) ? 1 : 0;
    return t;
}

__device__ __forceinline__ float eval_tap(const float* __restrict__ X, const Tap& t) {
    const float v000 = __ldg(X + t.b00);
    const float v001 = __ldg(X + t.b00 + t.dz);
    const float v010 = __ldg(X + t.b00 + t.dy);
    const float v011 = __ldg(X + t.b00 + t.dy + t.dz);
    const float v100 = __ldg(X + t.b00 + t.dx);
    const float v101 = __ldg(X + t.b00 + t.dx + t.dz);
    const float v110 = __ldg(X + t.b00 + t.dx + t.dy);
    const float v111 = __ldg(X + t.b00 + t.dx + t.dy + t.dz);
    const float v = interp8f(t.wcx, t.wcy, t.wcz,
                             v000, v001, v010, v011, v100, v101, v110, v111);
    return t.ok ? v : 0.f;
}

// Interior tap.
struct FTap { float wcx, wcy, wcz; int b; };

__device__ __forceinline__ FTap make_ftap(float di, float dj, float dk) {
    FTap t;
    const float fx = floorf(di), fy = floorf(dj), fz = floorf(dk);
    t.wcx = di - fx; t.wcy = dj - fy; t.wcz = dk - fz;
    t.b = ((int)fx << 16) | ((int)fy << 8) | (int)fz;
    return t;
}

__global__ void __launch_bounds__(256, 6)
warp_trilinear_direct4_kernel(const float* __restrict__ X, float* __restrict__ out) {
    const int k  = threadIdx.x;              // W (stride-1)
    const int jA = (blockIdx.x & 127) << 1;  // even j
    const int iA = (blockIdx.x >> 7) << 1;   // even i

    const float T00 = g_T[0], T01 = g_T[1], T02 = g_T[2],  T03 = g_T[3];
    const float T10 = g_T[4], T11 = g_T[5], T12 = g_T[6],  T13 = g_T[7];
    const float T20 = g_T[8], T21 = g_T[9], T22 = g_T[10], T23 = g_T[11];
    const float lo0 = g_T[12], lo1 = g_T[13], lo2 = g_T[14];
    const float hi0 = g_T[15], hi1 = g_T[16], hi2 = g_T[17];

    const float fi = (float)iA, fj = (float)jA, fk = (float)k;
    const float diA = fmaf(T00, fi, fmaf(T01, fj, fmaf(T02, fk, T03)));
    const float djA = fmaf(T10, fi, fmaf(T11, fj, fmaf(T12, fk, T13)));
    const float dkA = fmaf(T20, fi, fmaf(T21, fj, fmaf(T22, fk, T23)));

    const int idxA = (iA << 16) | (jA << 8) | k;

    // Interior test via precomputed corner bounds: 6 compares.
    const bool interior =
        (diA + lo0 > 0.f) & (diA + hi0 < 255.f) &
        (djA + lo1 > 0.f) & (djA + hi1 < 255.f) &
        (dkA + lo2 > 0.f) & (dkA + hi2 < 255.f);

    if (interior) {
        // ---------- FAST interior path ----------
        // 1) all taps first
        const FTap tA = make_ftap(diA, djA, dkA);
        const FTap tB = make_ftap(diA + T01, djA + T11, dkA + T21);
        const FTap tC = make_ftap(diA + T00, djA + T10, dkA + T20);
        const FTap tD = make_ftap(diA + T00 + T01, djA + T10 + T11,
                                  dkA + T20 + T21);

        // 2) ALL 20 unconditional loads, back-to-back (max MLP)
        const float a000 = __ldg(X + tA.b);
        const float a001 = __ldg(X + tA.b + 1);
        const float a010 = __ldg(X + tA.b + 256);
        const float a011 = __ldg(X + tA.b + 257);
        const float a100 = __ldg(X + tA.b + 65536);
        const float a101 = __ldg(X + tA.b + 65537);
        const float a110 = __ldg(X + tA.b + 65792);
        const float a111 = __ldg(X + tA.b + 65793);

        const float b010 = __ldg(X + tB.b + 256);
        const float b011 = __ldg(X + tB.b + 257);
        const float b110 = __ldg(X + tB.b + 65792);
        const float b111 = __ldg(X + tB.b + 65793);

        const float c100 = __ldg(X + tC.b + 65536);
        const float c101 = __ldg(X + tC.b + 65537);
        const float c110 = __ldg(X + tC.b + 65792);
        const float c111 = __ldg(X + tC.b + 65793);

        const float d010 = __ldg(X + tD.b + 256);
        const float d011 = __ldg(X + tD.b + 257);
        const float d110 = __ldg(X + tD.b + 65792);
        const float d111 = __ldg(X + tD.b + 65793);

        // 3) branchless reuse: predicated loads + selects (no divergence)
        const bool mB = (tB.b == tA.b + 256);
        const float b000 = mB ? a010 : __ldg(X + tB.b);
        const float b001 = mB ? a011 : __ldg(X + tB.b + 1);
        const float b100 = mB ? a110 : __ldg(X + tB.b + 65536);
        const float b101 = mB ? a111 : __ldg(X + tB.b + 65537);

        const bool mC = (tC.b == tA.b + 65536);
        const float c000 = mC ? a100 : __ldg(X + tC.b);
        const float c001 = mC ? a101 : __ldg(X + tC.b + 1);
        const float c010 = mC ? a110 : __ldg(X + tC.b + 256);
        const float c011 = mC ? a111 : __ldg(X + tC.b + 257);

        const bool mD = (tD.b == tC.b + 256);
        const float d000 = mD ? c010 : __ldg(X + tD.b);
        const float d001 = mD ? c011 : __ldg(X + tD.b + 1);
        const float d100 = mD ? c110 : __ldg(X + tD.b + 65536);
        const float d101 = mD ? c111 : __ldg(X + tD.b + 65537);

        // 4) interpolate + store
        out[idxA] = interp8f(tA.wcx, tA.wcy, tA.wcz,
                             a000, a001, a010, a011, a100, a101, a110, a111);
        out[idxA + 256] = interp8f(tB.wcx, tB.wcy, tB.wcz,
                             b000, b001, b010, b011, b100, b101, b110, b111);
        out[idxA + 65536] = interp8f(tC.wcx, tC.wcy, tC.wcz,
                             c000, c001, c010, c011, c100, c101, c110, c111);
        out[idxA + 65536 + 256] = interp8f(tD.wcx, tD.wcy, tD.wcz,
                             d000, d001, d010, d011, d100, d101, d110, d111);
    } else {
        // ---------- general boundary path ----------
        const Tap tA = make_tap(diA, djA, dkA);
        const Tap tB = make_tap(diA + T01, djA + T11, dkA + T21);
        const Tap tC = make_tap(diA + T00, djA + T10, dkA + T20);
        const Tap tD = make_tap(diA + T00 + T01, djA + T10 + T11,
                                dkA + T20 + T21);

        out[idxA]               = eval_tap(X, tA);
        out[idxA + 256]         = eval_tap(X, tB);
        out[idxA + 65536]       = eval_tap(X, tC);
        out[idxA + 65536 + 256] = eval_tap(X, tD);
    }
}

extern "C" void kernel_launch(void* const* d_in, const int* in_sizes, int n_in,
                              void* d_out, int out_size) {
    const float* image = (const float*)d_in[0];
    const float* rot   = (const float*)d_in[1];
    const float* tra   = (const float*)d_in[2];
    const float* refm  = (const float*)d_in[3];
    const float* flom  = (const float*)d_in[4];
    float* out = (float*)d_out;

    setup_T_kernel<<<1, 32>>>(rot, tra, refm, flom);
    warp_trilinear_direct4_kernel<<<(DIMD / 2) * (DIMH / 2), DIMW>>>(image, out);
}